// round 11
// baseline (speedup 1.0000x reference)
#include <cuda_runtime.h>

// ---------------------------------------------------------------------------
// 3-layer stacked LSTM (batch=1), T=4096, IN=64, H=1024, OUT=1, fp32.
//   k_init  : zero inter-CTA sync counters (graph replays reuse them)
//   k_gemm  : g_pre[t,4H] = A[t,K] @ W_ih.T + (b_ih + b_hh)
//   k_rec   : persistent 128-CTA recurrent loop, W_hh register-resident
//   k_final : out[0] = hs[T-1] . w_lin + b_lin
// ---------------------------------------------------------------------------

#define T_STEPS 4096
#define HID     1024
#define GATES   4096
#define NCTA    128
#define UNITS_PER_CTA 8

typedef unsigned long long ull;

// Static scratch (allocation-free).
__device__ float    g_pre[(size_t)T_STEPS * GATES];   // 64 MB
__device__ float    g_hsA[(size_t)T_STEPS * HID];     // 16 MB
__device__ float    g_hsB[(size_t)T_STEPS * HID];     // 16 MB
__device__ unsigned g_sync[96];                       // 3 counters, 128B apart

// ---- sm_103a packed-fp32 / memory helpers ---------------------------------

__device__ __forceinline__ void fma2(ull& d, ull a, ull b) {
    asm("fma.rn.f32x2 %0, %1, %2, %0;" : "+l"(d) : "l"(a), "l"(b));
}
__device__ __forceinline__ ull pack2(float x, float y) {
    ull r; asm("mov.b64 %0, {%1, %2};" : "=l"(r) : "f"(x), "f"(y)); return r;
}
__device__ __forceinline__ float2 unpack2(ull v) {
    float2 f; asm("mov.b64 {%0, %1}, %2;" : "=f"(f.x), "=f"(f.y) : "l"(v)); return f;
}
// L1-bypassing 8B load: h values are produced by other SMs mid-kernel.
__device__ __forceinline__ ull ldcg_u64(const float* p) {
    ull v; asm volatile("ld.global.cg.b64 %0, [%1];" : "=l"(v) : "l"(p)); return v;
}
__device__ __forceinline__ unsigned ld_acq(const unsigned* p) {
    unsigned v; asm volatile("ld.acquire.gpu.global.u32 %0, [%1];" : "=r"(v) : "l"(p)); return v;
}

// ---- init ------------------------------------------------------------------

__global__ void k_init() {
    if (threadIdx.x < 3) g_sync[threadIdx.x * 32] = 0u;
}

// ---- GEMM: g_pre[t, r] = sum_k A[t,k]*W[r,k] + b1[r] + b2[r] ---------------
// A: [T_STEPS, K] (K = 64 or 1024), W: [GATES, K]. 64x64 tile, 256 threads,
// 4x4 micro-tile with f32x2 packing.

#define GT  64
#define GR  64
#define GKC 16

__global__ void __launch_bounds__(256) k_gemm(
    const float* __restrict__ Ain, int src_sel, int K,
    const float* __restrict__ W,
    const float* __restrict__ b1, const float* __restrict__ b2)
{
    const float* A = (src_sel == 1) ? g_hsA : (src_sel == 2) ? g_hsB : Ain;
    float* C = g_pre;

    __shared__ float As[GKC][GT + 4];   // 68-float rows keep 16B alignment
    __shared__ float Ws[GKC][GR + 4];

    const int t0   = blockIdx.y * GT;
    const int r0   = blockIdx.x * GR;
    const int tx   = threadIdx.x & 15;        // micro col group (4 cols)
    const int ty   = threadIdx.x >> 4;        // micro row group (4 rows)
    const int lrow = threadIdx.x >> 2;        // 0..63 (load row)
    const int lcol = (threadIdx.x & 3) * 4;   // 0,4,8,12 (load col)

    ull acc[4][2];
#pragma unroll
    for (int i = 0; i < 4; ++i) { acc[i][0] = 0ull; acc[i][1] = 0ull; }

    for (int kk = 0; kk < K; kk += GKC) {
        float4 va = *(const float4*)(A + (size_t)(t0 + lrow) * K + kk + lcol);
        float4 vw = *(const float4*)(W + (size_t)(r0 + lrow) * K + kk + lcol);
        As[lcol + 0][lrow] = va.x; As[lcol + 1][lrow] = va.y;
        As[lcol + 2][lrow] = va.z; As[lcol + 3][lrow] = va.w;
        Ws[lcol + 0][lrow] = vw.x; Ws[lcol + 1][lrow] = vw.y;
        Ws[lcol + 2][lrow] = vw.z; Ws[lcol + 3][lrow] = vw.w;
        __syncthreads();
#pragma unroll
        for (int k = 0; k < GKC; ++k) {
            float4 a = *(const float4*)&As[k][4 * ty];
            const ull* wp = (const ull*)&Ws[k][4 * tx];
            ull w0 = wp[0], w1 = wp[1];
            ull ap;
            ap = pack2(a.x, a.x); fma2(acc[0][0], ap, w0); fma2(acc[0][1], ap, w1);
            ap = pack2(a.y, a.y); fma2(acc[1][0], ap, w0); fma2(acc[1][1], ap, w1);
            ap = pack2(a.z, a.z); fma2(acc[2][0], ap, w0); fma2(acc[2][1], ap, w1);
            ap = pack2(a.w, a.w); fma2(acc[3][0], ap, w0); fma2(acc[3][1], ap, w1);
        }
        __syncthreads();
    }

    const int r = r0 + 4 * tx;
    float4 bias;
    bias.x = b1[r + 0] + b2[r + 0];
    bias.y = b1[r + 1] + b2[r + 1];
    bias.z = b1[r + 2] + b2[r + 2];
    bias.w = b1[r + 3] + b2[r + 3];
#pragma unroll
    for (int i = 0; i < 4; ++i) {
        float2 p0 = unpack2(acc[i][0]);
        float2 p1 = unpack2(acc[i][1]);
        float4 o;
        o.x = p0.x + bias.x; o.y = p0.y + bias.y;
        o.z = p1.x + bias.z; o.w = p1.y + bias.w;
        *(float4*)(C + (size_t)(t0 + 4 * ty + i) * GATES + r) = o;
    }
}

// ---- Persistent recurrent kernel -------------------------------------------
// 128 CTAs x 256 threads (all resident). Warp w of CTA b owns hidden unit
// b*8+w and its 4 gate rows of W_hh. Lane l holds columns {64k+2l, 64k+2l+1}
// for k=0..15 of each gate row in registers (64 ull). Per step:
//   16 x ldcg(h pair) -> 64 fma2 -> 4x warp xor-reduce -> lane0 gate math ->
//   store h -> chip barrier (release atomic counter, acquire spin).

__global__ void __launch_bounds__(256, 1) k_rec(
    const float* __restrict__ whh, int hs_sel, int ctr_idx)
{
    float* hs = (hs_sel == 0) ? g_hsA : g_hsB;
    const float* pre = g_pre;
    unsigned* ctr = &g_sync[ctr_idx * 32];

    const int w    = threadIdx.x >> 5;
    const int l    = threadIdx.x & 31;
    const int unit = blockIdx.x * UNITS_PER_CTA + w;

    // Register-resident W_hh slice.
    ull wgt[4][16];
#pragma unroll
    for (int g = 0; g < 4; ++g) {
        const float* row = whh + (size_t)(g * HID + unit) * HID + 2 * l;
#pragma unroll
        for (int k = 0; k < 16; ++k)
            wgt[g][k] = *(const ull*)(row + 64 * k);
    }

    float c_state = 0.f;
    float p0 = 0.f, p1 = 0.f, p2 = 0.f, p3 = 0.f;
    if (l == 0) {
        p0 = pre[0 * HID + unit];
        p1 = pre[1 * HID + unit];
        p2 = pre[2 * HID + unit];
        p3 = pre[3 * HID + unit];
    }

    for (int t = 0; t < T_STEPS; ++t) {
        // Prefetch next step's pre (independent of the recurrence).
        float n0 = 0.f, n1 = 0.f, n2 = 0.f, n3 = 0.f;
        if (l == 0 && t + 1 < T_STEPS) {
            const float* pr = pre + (size_t)(t + 1) * GATES + unit;
            n0 = pr[0 * HID]; n1 = pr[1 * HID];
            n2 = pr[2 * HID]; n3 = pr[3 * HID];
        }

        float d0 = 0.f, d1 = 0.f, d2 = 0.f, d3 = 0.f;
        if (t > 0) {
            const float* hrow = hs + (size_t)(t - 1) * HID + 2 * l;
            ull a0 = 0ull, a1 = 0ull, a2 = 0ull, a3 = 0ull;
#pragma unroll
            for (int k = 0; k < 16; ++k) {
                ull hv = ldcg_u64(hrow + 64 * k);
                fma2(a0, wgt[0][k], hv);
                fma2(a1, wgt[1][k], hv);
                fma2(a2, wgt[2][k], hv);
                fma2(a3, wgt[3][k], hv);
            }
            float2 f0 = unpack2(a0), f1 = unpack2(a1);
            float2 f2 = unpack2(a2), f3 = unpack2(a3);
            d0 = f0.x + f0.y; d1 = f1.x + f1.y;
            d2 = f2.x + f2.y; d3 = f3.x + f3.y;
#pragma unroll
            for (int s = 16; s > 0; s >>= 1) {
                d0 += __shfl_xor_sync(0xffffffffu, d0, s);
                d1 += __shfl_xor_sync(0xffffffffu, d1, s);
                d2 += __shfl_xor_sync(0xffffffffu, d2, s);
                d3 += __shfl_xor_sync(0xffffffffu, d3, s);
            }
        }

        if (l == 0) {
            float gi = 1.f / (1.f + __expf(-(p0 + d0)));
            float gf = 1.f / (1.f + __expf(-(p1 + d1)));
            float gg = tanhf(p2 + d2);
            float go = 1.f / (1.f + __expf(-(p3 + d3)));
            c_state = gf * c_state + gi * gg;
            float h = go * tanhf(c_state);
            hs[(size_t)t * HID + unit] = h;
            p0 = n0; p1 = n1; p2 = n2; p3 = n3;
        }

        // Chip-wide step barrier: release arrive + acquire spin on a counter.
        __syncthreads();
        if (threadIdx.x == 0) {
            __threadfence();
            atomicAdd(ctr, 1u);
            const unsigned target = (unsigned)(t + 1) * NCTA;
            while (ld_acq(ctr) < target) { }
        }
        __syncthreads();
    }
}

// ---- Final linear layer ----------------------------------------------------

__global__ void k_final(const float* __restrict__ wlin,
                        const float* __restrict__ blin,
                        float* __restrict__ out)
{
    const float* h = g_hsA + (size_t)(T_STEPS - 1) * HID;
    __shared__ float red[8];
    float s = 0.f;
    for (int j = threadIdx.x; j < HID; j += 256)
        s += h[j] * wlin[j];
#pragma unroll
    for (int sh = 16; sh > 0; sh >>= 1)
        s += __shfl_xor_sync(0xffffffffu, s, sh);
    if ((threadIdx.x & 31) == 0) red[threadIdx.x >> 5] = s;
    __syncthreads();
    if (threadIdx.x < 8) {
        s = red[threadIdx.x];
#pragma unroll
        for (int sh = 4; sh > 0; sh >>= 1)
            s += __shfl_xor_sync(0x000000ffu, s, sh);
        if (threadIdx.x == 0) out[0] = s + blin[0];
    }
}

// ---- launch ----------------------------------------------------------------

extern "C" void kernel_launch(void* const* d_in, const int* in_sizes, int n_in,
                              void* d_out, int out_size)
{
    const float* seq   = (const float*)d_in[0];
    const float* w_ih0 = (const float*)d_in[1];
    const float* w_hh0 = (const float*)d_in[2];
    const float* b_ih0 = (const float*)d_in[3];
    const float* b_hh0 = (const float*)d_in[4];
    const float* w_ih1 = (const float*)d_in[5];
    const float* w_hh1 = (const float*)d_in[6];
    const float* b_ih1 = (const float*)d_in[7];
    const float* b_hh1 = (const float*)d_in[8];
    const float* w_ih2 = (const float*)d_in[9];
    const float* w_hh2 = (const float*)d_in[10];
    const float* b_ih2 = (const float*)d_in[11];
    const float* b_hh2 = (const float*)d_in[12];
    const float* w_lin = (const float*)d_in[13];
    const float* b_lin = (const float*)d_in[14];
    float* out = (float*)d_out;

    const dim3 ggrid(GATES / GR, T_STEPS / GT);

    k_init<<<1, 32>>>();
    // Layer 0: input dim 64
    k_gemm<<<ggrid, 256>>>(seq, 0, 64, w_ih0, b_ih0, b_hh0);
    k_rec<<<NCTA, 256>>>(w_hh0, /*hs_sel=*/0, /*ctr=*/0);
    // Layer 1: reads g_hsA
    k_gemm<<<ggrid, 256>>>(nullptr, 1, HID, w_ih1, b_ih1, b_hh1);
    k_rec<<<NCTA, 256>>>(w_hh1, /*hs_sel=*/1, /*ctr=*/1);
    // Layer 2: reads g_hsB
    k_gemm<<<ggrid, 256>>>(nullptr, 2, HID, w_ih2, b_ih2, b_hh2);
    k_rec<<<NCTA, 256>>>(w_hh2, /*hs_sel=*/0, /*ctr=*/2);
    // Output
    k_final<<<1, 256>>>(w_lin, b_lin, out);
}